// round 2
// baseline (speedup 1.0000x reference)
#include <cuda_runtime.h>
#include <math.h>

#define DD   512
#define NPOS 128
#define NB   32
#define LUT  256   // threads in LU kernel

// ---------------- device scratch (no allocations allowed) ----------------
__device__ float g_G[DD * DD];                 // 1 MB:   G = I - P P^T
__device__ float g_A[NPOS][DD * DD];           // 128 MB: per-step working matrices
__device__ float g_piv[NPOS][DD];              // pivots u_jj per step
__device__ int   g_posrank[DD];                // posrank[i] = j if positions[j]==i else INT_MAX
__device__ float g_picked[NPOS];               // log(picked prob) per step

// ---------------- kernel 0: position rank lookup ----------------
__global__ void posrank_kernel(const int* __restrict__ pos) {
    int t = threadIdx.x;
    if (t < DD) g_posrank[t] = 0x7fffffff;
    __syncthreads();
    if (t < NPOS) g_posrank[pos[t]] = t;
}

// ---------------- kernel 1: G = I - P P^T  (P is [DD, NPOS] row-major) ----------------
__global__ void gmat_kernel(const float* __restrict__ P) {
    __shared__ float sA[16][NPOS + 1];
    __shared__ float sB[16][NPOS + 1];
    int tx = threadIdx.x, ty = threadIdx.y;
    int tid = ty * 16 + tx;
    int i0 = blockIdx.y * 16, j0 = blockIdx.x * 16;

    for (int t = tid; t < 16 * NPOS; t += 256) {
        int r = t >> 7, c = t & (NPOS - 1);
        sA[r][c] = P[(i0 + r) * NPOS + c];
        sB[r][c] = P[(j0 + r) * NPOS + c];
    }
    __syncthreads();

    float acc = 0.0f;
#pragma unroll 8
    for (int c = 0; c < NPOS; c++) acc += sA[ty][c] * sB[tx][c];

    int i = i0 + ty, j = j0 + tx;
    g_G[i * DD + j] = ((i == j) ? 1.0f : 0.0f) - acc;
}

// ---------------- kernel 2: init A_k = G - diag(occ_prefix_k), leading n_k block ----------------
__global__ void init_kernel() {
    int k = blockIdx.y;
    int n = DD - NPOS + k + 1;
    int r0 = blockIdx.x * 32;
    for (int r = r0; r < r0 + 32 && r < n; r++) {
        int dec = (g_posrank[r] < k) ? 1 : 0;
        float* dst = g_A[k] + (size_t)r * DD;
        const float* src = g_G + (size_t)r * DD;
        for (int j = threadIdx.x; j < n; j += blockDim.x) {
            float v = src[j];
            if (j == r && dec) v -= 1.0f;
            dst[j] = v;
        }
    }
}

// ---------------- kernel 3: blocked unpivoted elimination, one CTA per k ----------------
// SMEM: sm = unscaled panel M (rows x NB, stride 33), sl = scaled L panel.
// Trailing update uses symmetry: U[c,j] = d_c * L[j,c] = M[j,c]  =>  C[i,j] -= L[i,c]*M[j,c].
__global__ void lu_kernel() {
    int k = blockIdx.x;
    int n = DD - NPOS + k + 1;
    float* A = g_A[k];
    extern __shared__ float smem[];
    float* sm = smem;              // [rows][33]
    float* sl = smem + DD * 33;    // [rows][33]
    const int tid = threadIdx.x;

    for (int p = 0; p < n; p += NB) {
        int pw   = min(NB, n - p);
        int rows = n - p;

        // load panel (coalesced: 32 consecutive floats per row)
        for (int t = tid; t < rows * NB; t += LUT) {
            int r = t >> 5, c = t & 31;
            float v = (c < pw) ? A[(size_t)(p + r) * DD + (p + c)] : 0.0f;
            sm[r * 33 + c] = v;
        }
        __syncthreads();

        // factor panel columns
        for (int c = 0; c < pw; c++) {
            float d = sm[c * 33 + c];
            float inv = 1.0f / d;
            for (int i = c + 1 + tid; i < rows; i += LUT) {
                float m = sm[i * 33 + c];
                float l = m * inv;
                sl[i * 33 + c] = l;
#pragma unroll
                for (int j = c + 1; j < NB; j++) {
                    if (j < pw) sm[i * 33 + j] -= l * sm[c * 33 + j];
                }
            }
            __syncthreads();
        }

        // record pivots (diagonal of M panel, untouched after its column factored)
        if (tid < pw) g_piv[k][p + tid] = sm[tid * 33 + tid];

        // trailing symmetric rank-pw update: C[i,j] -= sum_c L[i,c] * M[j,c]
        int tr0 = p + pw;
        int tsz = n - tr0;
        if (tsz > 0) {
            int tx = tid & 15, ty = tid >> 4;   // 16x16 thread grid
            for (int jb = 0; jb < tsz; jb += 128) {
                for (int ib = 0; ib < tsz; ib += 128) {
                    int iidx[8], jidx[8];
                    bool iv[8], jv[8];
#pragma unroll
                    for (int u = 0; u < 8; u++) {
                        int il = ib + ty + 16 * u;
                        iv[u] = (il < tsz); iidx[u] = iv[u] ? il : 0;
                    }
#pragma unroll
                    for (int v = 0; v < 8; v++) {
                        int jl = jb + tx + 16 * v;
                        jv[v] = (jl < tsz); jidx[v] = jv[v] ? jl : 0;
                    }
                    float acc[8][8];
#pragma unroll
                    for (int u = 0; u < 8; u++)
#pragma unroll
                        for (int v = 0; v < 8; v++)
                            acc[u][v] = (iv[u] && jv[v])
                                ? A[(size_t)(tr0 + iidx[u]) * DD + tr0 + jidx[v]] : 0.0f;

                    for (int c = 0; c < pw; c++) {
                        float Lr[8], Mr[8];
#pragma unroll
                        for (int u = 0; u < 8; u++) Lr[u] = sl[(pw + iidx[u]) * 33 + c];
#pragma unroll
                        for (int v = 0; v < 8; v++) Mr[v] = sm[(pw + jidx[v]) * 33 + c];
#pragma unroll
                        for (int u = 0; u < 8; u++)
#pragma unroll
                            for (int v = 0; v < 8; v++)
                                acc[u][v] -= Lr[u] * Mr[v];
                    }
#pragma unroll
                    for (int u = 0; u < 8; u++)
#pragma unroll
                        for (int v = 0; v < 8; v++)
                            if (iv[u] && jv[v])
                                A[(size_t)(tr0 + iidx[u]) * DD + tr0 + jidx[v]] = acc[u][v];
                }
            }
        }
        __syncthreads();
    }
}

// ---------------- kernel 4: windowed cumprod -> probs rows, picked logs ----------------
__global__ void probs_kernel(const int* __restrict__ pos, float* __restrict__ out) {
    int k = blockIdx.x;
    float* row = out + (size_t)k * DD;
    for (int i = threadIdx.x; i < DD; i += blockDim.x) row[i] = 0.0f;
    __syncthreads();
    if (threadIdx.x == 0) {
        int xmin = (k == 0) ? 0 : (pos[k - 1] + 1);
        int xmax = DD - NPOS + k + 1;
        int pk = pos[k];
        float c = 1.0f;
        float picked = 0.0f;
        for (int i = xmin; i < xmax; i++) {
            float u = g_piv[k][i];
            float pr = c * (1.0f - u);
            pr = (fabsf(pr) > 1e-15f) ? pr : 0.0f;
            row[i] = pr;
            if (i == pk) picked = pr;
            c *= u;
        }
        g_picked[k] = logf(picked);
    }
}

// ---------------- kernel 5: deterministic sequential log-sum ----------------
__global__ void finalize_kernel(float* __restrict__ out, int out_size) {
    if (threadIdx.x == 0) {
        float s = 0.0f;
        for (int k = 0; k < NPOS; k++) s += g_picked[k];
        out[out_size - 1] = s;
    }
}

// ---------------- launch ----------------
extern "C" void kernel_launch(void* const* d_in, const int* in_sizes, int n_in,
                              void* d_out, int out_size) {
    const float* P   = (const float*)d_in[0];
    const int*   pos = (const int*)d_in[1];
    float*       out = (float*)d_out;

    size_t lu_smem = (size_t)2 * DD * 33 * sizeof(float);   // 135168 B
    cudaFuncSetAttribute(lu_kernel, cudaFuncAttributeMaxDynamicSharedMemorySize, (int)lu_smem);

    posrank_kernel<<<1, 512>>>(pos);
    gmat_kernel<<<dim3(DD / 16, DD / 16), dim3(16, 16)>>>(P);
    init_kernel<<<dim3(16, NPOS), 256>>>();
    lu_kernel<<<NPOS, LUT, lu_smem>>>();
    probs_kernel<<<NPOS, 256>>>(pos, out);
    finalize_kernel<<<1, 32>>>(out, out_size);
}